// round 13
// baseline (speedup 1.0000x reference)
#include <cuda_runtime.h>
#include <cuda_bf16.h>
#include <math.h>
#include <stdint.h>

// TopkRouter: logits = X @ W^T + b ; top-8 ; masked softmax.
// X: [32768, 2048] f32, W: [64, 2048] f32, b: [64] f32
// out: probs [32768,64] f32 then indices [32768,8] (as f32).
//
// main: 3xTF32 mma.sync (m16n8k8, hh+hl+lh, fp32 accum), logit err ~2e-5.
//       flag tokens whose top-9 adjacent gap < TAU.
// fixup: flagged tokens recomputed bitwise in the reference order
//        (XLA:CPU Eigen gebp: ascending-k fp32 FMA in 320-wide panels,
//        master += panel, 128 remainder, bias last).

#define TOKENS 32768
#define EMBED 2048
#define NEXP 64
#define TOPK 8
#define TPB 256
#define NTHREADS 512
#define KT 32
#define NTILES (EMBED / KT)          // 64
#define TAU 1e-3f
#define LG_STRIDE 65
#define XS_STRIDE 36

// ---- main smem layout (floats) ----
#define XF0 0                         // 256*36 = 9216
#define XF1 9216
#define AH_OFF 18432                  // 8192
#define AL_OFF 26624                  // 8192
#define BF0 34816                     // 4096
#define BF1 38912                     // 4096
#define SIDX_OFF 43008                // 256*8
#define SBIAS_OFF 45056               // 64
#define SMEM1_FLOATS 45120            // 180480 B

__device__ float w_frag[NTILES * 4096];     // frag-ordered tf32 hi/lo W (1MB)
__device__ int d_flag_count;
__device__ int d_flag_list[TOKENS];

static __device__ __forceinline__ float tf32r(float x) {
    float y;
    asm("cvt.rna.tf32.f32 %0, %1;" : "=f"(y) : "f"(x));
    return y;
}
static __device__ __forceinline__ void cp_async16(uint32_t saddr, const void* g) {
    asm volatile("cp.async.cg.shared.global [%0], [%1], 16;" :: "r"(saddr), "l"(g));
}
static __device__ __forceinline__ void cp_commit() {
    asm volatile("cp.async.commit_group;" ::: "memory");
}
static __device__ __forceinline__ void cp_wait0() {
    asm volatile("cp.async.wait_group 0;" ::: "memory");
}
static __device__ __forceinline__ void mma8(float* c, uint32_t a0, uint32_t a1,
                                            uint32_t a2, uint32_t a3,
                                            uint32_t b0, uint32_t b1) {
    asm volatile(
        "mma.sync.aligned.m16n8k8.row.col.f32.tf32.tf32.f32 "
        "{%0,%1,%2,%3}, {%4,%5,%6,%7}, {%8,%9}, {%0,%1,%2,%3};"
        : "+f"(c[0]), "+f"(c[1]), "+f"(c[2]), "+f"(c[3])
        : "r"(a0), "r"(a1), "r"(a2), "r"(a3), "r"(b0), "r"(b1));
}

__global__ void reset_flags_kernel() { d_flag_count = 0; }

// W -> frag-ordered tf32 hi/lo in gmem.
// slot(t,s,j,lane,c): n = 8j + lane/4 ; k = 32t + 8s + (lane%4) + 4*(c&1);
// c in {0,1}=hi b0/b1, {2,3}=lo b0/b1.
__global__ void w_convert_kernel(const float* __restrict__ W) {
    int idx = blockIdx.x * blockDim.x + threadIdx.x;   // 64*2048
    if (idx >= NEXP * EMBED) return;
    int n = idx >> 11, k = idx & 2047;
    float w = W[idx];
    float hi = tf32r(w);
    float lo = tf32r(w - hi);
    int t = k >> 5, s = (k >> 3) & 3, j = n >> 3;
    int lane = (n & 7) * 4 + (k & 3);
    int chi = (k >> 2) & 1;
    int base = t * 4096 + ((s * 8 + j) * 32 + lane) * 4;
    w_frag[base + chi] = hi;
    w_frag[base + 2 + chi] = lo;
}

__global__ __launch_bounds__(NTHREADS, 1)
void router_main_kernel(const float* __restrict__ X,
                        const float* __restrict__ W,
                        const float* __restrict__ B,
                        float* __restrict__ probs_out,
                        float* __restrict__ idx_out) {
    extern __shared__ float smem[];
    float* logits = smem;             // reuses XF region after GEMM (16640 < 18432)
    float* sidx   = smem + SIDX_OFF;
    float* sbias  = smem + SBIAS_OFF;

    const int tid  = threadIdx.x;
    const int lane = tid & 31;
    const int w    = tid >> 5;        // 0..15
    const int wm   = w & 7;           // token group: tokens 32wm..32wm+31
    const int wn   = w >> 3;          // n-half: experts 32wn..32wn+31
    const int tok0 = blockIdx.x * TPB;
    const uint32_t sb = (uint32_t)__cvta_generic_to_shared(smem);

    if (tid < NEXP) sbias[tid] = B[tid];

    // X stage loader lanes: 256 rows x 8 float4 chunks
    const int xt = tid >> 1;
    const int xh = tid & 1;
    const float* Xg = X + (size_t)(tok0 + xt) * EMBED;

    float c[2][4][4];
#pragma unroll
    for (int a = 0; a < 2; a++)
#pragma unroll
        for (int b = 0; b < 4; b++)
#pragma unroll
            for (int r = 0; r < 4; r++) c[a][b][r] = 0.0f;

    // prologue: stage tile 0 (X + B frags)
#pragma unroll
    for (int r = 0; r < 4; r++) {
        int cc = xh * 4 + r;
        cp_async16(sb + 4u * (XF0 + (uint32_t)xt * XS_STRIDE + 4 * cc), Xg + 4 * cc);
    }
#pragma unroll
    for (int r = 0; r < 2; r++) {
        int i = tid + 512 * r;        // uint4 index 0..1023
        cp_async16(sb + 4u * (BF0 + 4 * i), w_frag + 4 * i);
    }
    cp_commit();

    const uint4* AH4 = reinterpret_cast<const uint4*>(smem + AH_OFF);
    const uint4* AL4 = reinterpret_cast<const uint4*>(smem + AL_OFF);

    for (int t = 0; t < NTILES; t++) {
        cp_wait0();
        __syncthreads();              // tile t staged; mma(t-1) complete

        // issue tile t+1 stage
        if (t + 1 < NTILES) {
            const uint32_t xb = ((t + 1) & 1) ? XF1 : XF0;
            const uint32_t bb = ((t + 1) & 1) ? BF1 : BF0;
            const float* Xn = Xg + (size_t)(t + 1) * KT;
#pragma unroll
            for (int r = 0; r < 4; r++) {
                int cc = xh * 4 + r;
                cp_async16(sb + 4u * (xb + (uint32_t)xt * XS_STRIDE + 4 * cc), Xn + 4 * cc);
            }
            const float* Wn = w_frag + (size_t)(t + 1) * 4096;
#pragma unroll
            for (int r = 0; r < 2; r++) {
                int i = tid + 512 * r;
                cp_async16(sb + 4u * (bb + 4 * i), Wn + 4 * i);
            }
            cp_commit();
        }

        // convert X stage -> AH/AL in fragment order (conflict-free stores)
        {
            const float* Xf = smem + ((t & 1) ? XF1 : XF0);
            float* AHf = smem + AH_OFF;
            float* ALf = smem + AL_OFF;
#pragma unroll
            for (int q = 0; q < 16; q++) {
                int v = tid + 512 * q;             // 0..8191
                int reg = v & 3;
                int fl  = (v >> 2) & 31;
                int s   = (v >> 7) & 3;
                int g16 = v >> 9;
                int m = (g16 << 4) + (fl >> 2) + ((reg & 1) << 3);
                int k = (s << 3) + (fl & 3) + ((reg >> 1) << 2);
                float x = Xf[m * XS_STRIDE + k];
                float hi = tf32r(x);
                AHf[v] = hi;
                ALf[v] = tf32r(x - hi);
            }
        }
        __syncthreads();

        // mma phase
        const uint4* BF4 = reinterpret_cast<const uint4*>(smem + ((t & 1) ? BF1 : BF0));
        const int g0 = 2 * wm, g1 = 2 * wm + 1;
#pragma unroll
        for (int s = 0; s < 4; s++) {
            uint4 ah0 = AH4[(g0 * 4 + s) * 32 + lane];
            uint4 al0 = AL4[(g0 * 4 + s) * 32 + lane];
            uint4 ah1 = AH4[(g1 * 4 + s) * 32 + lane];
            uint4 al1 = AL4[(g1 * 4 + s) * 32 + lane];
#pragma unroll
            for (int j = 0; j < 4; j++) {
                uint4 b = BF4[(s * 8 + 4 * wn + j) * 32 + lane];
                mma8(c[0][j], ah0.x, ah0.y, ah0.z, ah0.w, b.x, b.y);   // hh
                mma8(c[0][j], ah0.x, ah0.y, ah0.z, ah0.w, b.z, b.w);   // hl
                mma8(c[0][j], al0.x, al0.y, al0.z, al0.w, b.x, b.y);   // lh
                mma8(c[1][j], ah1.x, ah1.y, ah1.z, ah1.w, b.x, b.y);
                mma8(c[1][j], ah1.x, ah1.y, ah1.z, ah1.w, b.z, b.w);
                mma8(c[1][j], al1.x, al1.y, al1.z, al1.w, b.x, b.y);
            }
        }
    }
    __syncthreads();   // all mma done; stage buffers dead -> logits region free

    // epilogue: C frags + bias -> logits smem
#pragma unroll
    for (int mf = 0; mf < 2; mf++) {
#pragma unroll
        for (int j = 0; j < 4; j++) {
            int row0 = 32 * wm + 16 * mf + (lane >> 2);
            int e0   = 32 * wn + 8 * j + 2 * (lane & 3);
            logits[row0 * LG_STRIDE + e0]       = c[mf][j][0] + sbias[e0];
            logits[row0 * LG_STRIDE + e0 + 1]   = c[mf][j][1] + sbias[e0 + 1];
            logits[(row0 + 8) * LG_STRIDE + e0]     = c[mf][j][2] + sbias[e0];
            logits[(row0 + 8) * LG_STRIDE + e0 + 1] = c[mf][j][3] + sbias[e0 + 1];
        }
    }
    __syncthreads();

    // top-9 flag + top-8 softmax (token = tid < 256)
    if (tid < TPB) {
        float* row = logits + tid * LG_STRIDE;
        float vals[TOPK + 1];
        int   inds[TOPK + 1];
#pragma unroll
        for (int s = 0; s < TOPK + 1; s++) {
            float best = -INFINITY;
            int bi = 0;
            for (int j = 0; j < NEXP; j++) {
                float v = row[j];
                if (v > best) { best = v; bi = j; }
            }
            vals[s] = best; inds[s] = bi; row[bi] = -INFINITY;
        }
        bool flag = false;
#pragma unroll
        for (int s = 0; s < TOPK; s++)
            if (vals[s] - vals[s + 1] < TAU) flag = true;
        if (flag) {
            int pos = atomicAdd(&d_flag_count, 1);
            d_flag_list[pos] = tok0 + tid;
        }
        float m = vals[0], e[TOPK], sum = 0.0f;
#pragma unroll
        for (int s = 0; s < TOPK; s++) { e[s] = expf(vals[s] - m); sum += e[s]; }
        float inv = 1.0f / sum;
        for (int j = 0; j < NEXP; j++) row[j] = 0.0f;
#pragma unroll
        for (int s = 0; s < TOPK; s++) {
            row[inds[s]] = e[s] * inv;
            sidx[tid * TOPK + s] = (float)inds[s];
        }
    }
    __syncthreads();

    for (int i = tid; i < TPB * NEXP; i += NTHREADS) {
        int tk = i >> 6, e = i & 63;
        probs_out[(size_t)(tok0 + tk) * NEXP + e] = logits[tk * LG_STRIDE + e];
    }
    if (idx_out)
        for (int i = tid; i < TPB * TOPK; i += NTHREADS)
            idx_out[(size_t)tok0 * TOPK + i] = sidx[i];
}

// ---- fixup: exact Eigen-order recompute, 8 flagged tokens per group ----
#define FXT 8
#define FX_XP 0                       // 8*320 = 2560
#define FX_WP 2560                    // 320*65 = 20800
#define FX_LR 23360                   // 8*64 = 512
#define FX_TOK 23872                  // 8 (ints)
#define SMEM2_FLOATS 23880            // 95520 B

__global__ __launch_bounds__(NTHREADS)
void router_fixup_kernel(const float* __restrict__ X,
                         const float* __restrict__ W,
                         const float* __restrict__ B,
                         float* __restrict__ probs_out,
                         float* __restrict__ idx_out) {
    extern __shared__ float smem[];
    float* xp = smem + FX_XP;
    float* wp = smem + FX_WP;
    float* lr = smem + FX_LR;
    int* toks = reinterpret_cast<int*>(smem + FX_TOK);
    const int tid = threadIdx.x;
    const int n = d_flag_count;

    for (int base = blockIdx.x * FXT; base < n; base += gridDim.x * FXT) {
        const int cnt = (n - base < FXT) ? (n - base) : FXT;
        if (tid < cnt) toks[tid] = d_flag_list[base + tid];

        const int ti = tid >> 6;      // token slot 0..7
        const int e  = tid & 63;      // expert
        float mst = 0.0f;

        for (int k0 = 0; k0 < EMBED; k0 += 320) {
            const int len = (EMBED - k0 < 320) ? (EMBED - k0) : 320;
            __syncthreads();          // prior compute/select done; toks visible
            for (int i = tid; i < NEXP * len; i += NTHREADS) {
                int ee = i / len, k = i % len;
                wp[k * 65 + ee] = W[(size_t)ee * EMBED + k0 + k];
            }
            for (int i = tid; i < cnt * len; i += NTHREADS) {
                int tt = i / len, k = i % len;
                xp[tt * 320 + k] = X[(size_t)toks[tt] * EMBED + k0 + k];
            }
            __syncthreads();
            if (ti < cnt) {
                float til = 0.0f;
                for (int k = 0; k < len; k++)
                    til = fmaf(xp[ti * 320 + k], wp[k * 65 + e], til);
                mst = mst + til;      // panel flush, ascending panels
            }
        }
        if (ti < cnt) lr[ti * 64 + e] = mst + B[e];
        __syncthreads();

        if (tid < cnt) {
            const int tok = toks[tid];
            float* lrow = lr + tid * 64;
            float vals[TOPK]; int inds[TOPK];
#pragma unroll
            for (int s = 0; s < TOPK; s++) {
                float best = -INFINITY; int bi = 0;
                for (int j = 0; j < NEXP; j++) {
                    float v = lrow[j];
                    if (v > best) { best = v; bi = j; }
                }
                vals[s] = best; inds[s] = bi; lrow[bi] = -INFINITY;
            }
            float m = vals[0], ex[TOPK], sum = 0.0f;
#pragma unroll
            for (int s = 0; s < TOPK; s++) { ex[s] = expf(vals[s] - m); sum += ex[s]; }
            float inv = 1.0f / sum;
            for (int j = 0; j < NEXP; j++) probs_out[(size_t)tok * NEXP + j] = 0.0f;
#pragma unroll
            for (int s = 0; s < TOPK; s++) {
                probs_out[(size_t)tok * NEXP + inds[s]] = ex[s] * inv;
                if (idx_out) idx_out[(size_t)tok * TOPK + s] = (float)inds[s];
            }
        }
        __syncthreads();
    }
}

extern "C" void kernel_launch(void* const* d_in, const int* in_sizes, int n_in,
                              void* d_out, int out_size) {
    const float* X = (const float*)d_in[0];
    const float* W = (const float*)d_in[1];
    const float* B = (const float*)d_in[2];
    float* out = (float*)d_out;

    const long long PROBS_ELEMS = (long long)TOKENS * NEXP;
    const long long IDX_ELEMS   = (long long)TOKENS * TOPK;
    float* idx_out = nullptr;
    if ((long long)out_size >= PROBS_ELEMS + IDX_ELEMS) idx_out = out + PROBS_ELEMS;

    static bool attr_done = false;
    if (!attr_done) {
        cudaFuncSetAttribute(router_main_kernel,
                             cudaFuncAttributeMaxDynamicSharedMemorySize, SMEM1_FLOATS * 4);
        cudaFuncSetAttribute(router_fixup_kernel,
                             cudaFuncAttributeMaxDynamicSharedMemorySize, SMEM2_FLOATS * 4);
        attr_done = true;
    }
    reset_flags_kernel<<<1, 1>>>();
    w_convert_kernel<<<(NEXP * EMBED + 255) / 256, 256>>>(W);
    router_main_kernel<<<TOKENS / TPB, NTHREADS, SMEM1_FLOATS * 4>>>(X, W, B, out, idx_out);
    router_fixup_kernel<<<64, NTHREADS, SMEM2_FLOATS * 4>>>(X, W, B, out, idx_out);
}

// round 15
// speedup vs baseline: 1.0473x; 1.0473x over previous
#include <cuda_runtime.h>
#include <cuda_bf16.h>
#include <math.h>
#include <stdint.h>

// TopkRouter: logits = X @ W^T + b ; top-8 ; masked softmax.
// main: 3xTF32 mma.sync (m16n8k8, hh+hl+lh, fp32 accum), logit err ~1e-6.
//       flag tokens whose top-9 adjacent gap < TAU.
// fixup: flagged tokens recomputed bitwise in the reference order
//        (XLA:CPU Eigen gebp: ascending-k fp32 FMA in 320-wide panels,
//        master += panel, 128 remainder, bias last).

#define TOKENS 32768
#define EMBED 2048
#define NEXP 64
#define TOPK 8
#define TPB 128
#define NTHREADS 256
#define KT 32
#define NTILES (EMBED / KT)          // 64
#define TAU 1e-3f
#define LG_STRIDE 65
#define XS_STRIDE 36

// ---- main smem layout (floats) ----
#define XF0 0                         // 128*36 = 4608
#define XF1 4608
#define AH_OFF 9216                   // 128*32 = 4096
#define AL_OFF 13312
#define BF0 17408                     // 4096
#define BF1 21504
#define SIDX_OFF 25600                // 128*8
#define SBIAS_OFF 26624               // 64
#define SMEM1_FLOATS 26688            // 106752 B -> 2 CTA/SM

__device__ float w_frag[NTILES * 4096];     // frag-ordered tf32 hi/lo W (1MB)
__device__ int d_flag_count;
__device__ int d_flag_list[TOKENS];

static __device__ __forceinline__ float tf32r(float x) {
    float y;
    asm("cvt.rna.tf32.f32 %0, %1;" : "=f"(y) : "f"(x));
    return y;
}
static __device__ __forceinline__ void cp_async16(uint32_t saddr, const void* g) {
    asm volatile("cp.async.cg.shared.global [%0], [%1], 16;" :: "r"(saddr), "l"(g));
}
static __device__ __forceinline__ void cp_commit() {
    asm volatile("cp.async.commit_group;" ::: "memory");
}
static __device__ __forceinline__ void cp_wait0() {
    asm volatile("cp.async.wait_group 0;" ::: "memory");
}
static __device__ __forceinline__ void mma8(float* c, uint32_t a0, uint32_t a1,
                                            uint32_t a2, uint32_t a3,
                                            uint32_t b0, uint32_t b1) {
    asm volatile(
        "mma.sync.aligned.m16n8k8.row.col.f32.tf32.tf32.f32 "
        "{%0,%1,%2,%3}, {%4,%5,%6,%7}, {%8,%9}, {%0,%1,%2,%3};"
        : "+f"(c[0]), "+f"(c[1]), "+f"(c[2]), "+f"(c[3])
        : "r"(a0), "r"(a1), "r"(a2), "r"(a3), "r"(b0), "r"(b1));
}

__global__ void reset_flags_kernel() { d_flag_count = 0; }

// W -> frag-ordered tf32 hi/lo in gmem.
__global__ void w_convert_kernel(const float* __restrict__ W) {
    int idx = blockIdx.x * blockDim.x + threadIdx.x;   // 64*2048
    if (idx >= NEXP * EMBED) return;
    int n = idx >> 11, k = idx & 2047;
    float w = W[idx];
    float hi = tf32r(w);
    float lo = tf32r(w - hi);
    int t = k >> 5, s = (k >> 3) & 3, j = n >> 3;
    int lane = (n & 7) * 4 + (k & 3);
    int chi = (k >> 2) & 1;
    int base = t * 4096 + ((s * 8 + j) * 32 + lane) * 4;
    w_frag[base + chi] = hi;
    w_frag[base + 2 + chi] = lo;
}

__global__ __launch_bounds__(NTHREADS, 2)
void router_main_kernel(const float* __restrict__ X,
                        const float* __restrict__ W,
                        const float* __restrict__ B,
                        float* __restrict__ probs_out,
                        float* __restrict__ idx_out) {
    extern __shared__ float smem[];
    float* logits = smem;             // reuses XF region after GEMM (8320 < 9216)
    float* sidx   = smem + SIDX_OFF;
    float* sbias  = smem + SBIAS_OFF;

    const int tid  = threadIdx.x;
    const int lane = tid & 31;
    const int w    = tid >> 5;        // 0..7
    const int wm   = w & 3;           // token group: rows 32wm..32wm+31
    const int wn   = w >> 2;          // n-half: experts 32wn..32wn+31
    const int tok0 = blockIdx.x * TPB;
    const uint32_t sb = (uint32_t)__cvta_generic_to_shared(smem);

    if (tid < NEXP) sbias[tid] = B[tid];

    // X stage loader lanes: 128 rows x 8 float4 chunks
    const int xt = tid >> 1;
    const int xh = tid & 1;
    const float* Xg = X + (size_t)(tok0 + xt) * EMBED;

    float c[2][4][4];
#pragma unroll
    for (int a = 0; a < 2; a++)
#pragma unroll
        for (int b = 0; b < 4; b++)
#pragma unroll
            for (int r = 0; r < 4; r++) c[a][b][r] = 0.0f;

    // prologue: stage tile 0 (X + B frags)
#pragma unroll
    for (int r = 0; r < 4; r++) {
        int cc = xh * 4 + r;
        cp_async16(sb + 4u * (XF0 + (uint32_t)xt * XS_STRIDE + 4 * cc), Xg + 4 * cc);
    }
#pragma unroll
    for (int r = 0; r < 4; r++) {
        int i = tid + 256 * r;        // uint4 index 0..1023
        cp_async16(sb + 4u * (BF0 + 4 * i), w_frag + 4 * i);
    }
    cp_commit();

    const uint4* AH4 = reinterpret_cast<const uint4*>(smem + AH_OFF);
    const uint4* AL4 = reinterpret_cast<const uint4*>(smem + AL_OFF);

    for (int t = 0; t < NTILES; t++) {
        cp_wait0();
        __syncthreads();              // tile t staged; mma(t-1) complete

        // issue tile t+1 stage
        if (t + 1 < NTILES) {
            const uint32_t xb = ((t + 1) & 1) ? XF1 : XF0;
            const uint32_t bb = ((t + 1) & 1) ? BF1 : BF0;
            const float* Xn = Xg + (size_t)(t + 1) * KT;
#pragma unroll
            for (int r = 0; r < 4; r++) {
                int cc = xh * 4 + r;
                cp_async16(sb + 4u * (xb + (uint32_t)xt * XS_STRIDE + 4 * cc), Xn + 4 * cc);
            }
            const float* Wn = w_frag + (size_t)(t + 1) * 4096;
#pragma unroll
            for (int r = 0; r < 4; r++) {
                int i = tid + 256 * r;
                cp_async16(sb + 4u * (bb + 4 * i), Wn + 4 * i);
            }
            cp_commit();
        }

        // convert X stage -> AH/AL in fragment order (conflict-free both sides)
        {
            const float* Xf = smem + ((t & 1) ? XF1 : XF0);
            float* AHf = smem + AH_OFF;
            float* ALf = smem + AL_OFF;
#pragma unroll
            for (int q = 0; q < 16; q++) {
                int v = tid + 256 * q;             // 0..4095
                int reg = v & 3;
                int fl  = (v >> 2) & 31;
                int s   = (v >> 7) & 3;
                int g16 = v >> 9;                  // 0..7
                int m = (g16 << 4) + (fl >> 2) + ((reg & 1) << 3);
                int k = (s << 3) + (fl & 3) + ((reg >> 1) << 2);
                float x = Xf[m * XS_STRIDE + k];
                float hi = tf32r(x);
                AHf[v] = hi;
                ALf[v] = tf32r(x - hi);
            }
        }
        __syncthreads();

        // mma phase
        const uint4* BF4 = reinterpret_cast<const uint4*>(smem + ((t & 1) ? BF1 : BF0));
        const int g0 = 2 * wm, g1 = 2 * wm + 1;
#pragma unroll
        for (int s = 0; s < 4; s++) {
            uint4 ah0 = AH4[(g0 * 4 + s) * 32 + lane];
            uint4 al0 = AL4[(g0 * 4 + s) * 32 + lane];
            uint4 ah1 = AH4[(g1 * 4 + s) * 32 + lane];
            uint4 al1 = AL4[(g1 * 4 + s) * 32 + lane];
#pragma unroll
            for (int j = 0; j < 4; j++) {
                uint4 b = BF4[(s * 8 + 4 * wn + j) * 32 + lane];
                mma8(c[0][j], ah0.x, ah0.y, ah0.z, ah0.w, b.x, b.y);   // hh
                mma8(c[0][j], ah0.x, ah0.y, ah0.z, ah0.w, b.z, b.w);   // hl
                mma8(c[0][j], al0.x, al0.y, al0.z, al0.w, b.x, b.y);   // lh
                mma8(c[1][j], ah1.x, ah1.y, ah1.z, ah1.w, b.x, b.y);
                mma8(c[1][j], ah1.x, ah1.y, ah1.z, ah1.w, b.z, b.w);
                mma8(c[1][j], al1.x, al1.y, al1.z, al1.w, b.x, b.y);
            }
        }
    }
    __syncthreads();   // all mma done; stage buffers dead -> logits region free

    // epilogue: C frags + bias -> logits smem
#pragma unroll
    for (int mf = 0; mf < 2; mf++) {
#pragma unroll
        for (int j = 0; j < 4; j++) {
            int row0 = 32 * wm + 16 * mf + (lane >> 2);
            int e0   = 32 * wn + 8 * j + 2 * (lane & 3);
            logits[row0 * LG_STRIDE + e0]       = c[mf][j][0] + sbias[e0];
            logits[row0 * LG_STRIDE + e0 + 1]   = c[mf][j][1] + sbias[e0 + 1];
            logits[(row0 + 8) * LG_STRIDE + e0]     = c[mf][j][2] + sbias[e0];
            logits[(row0 + 8) * LG_STRIDE + e0 + 1] = c[mf][j][3] + sbias[e0 + 1];
        }
    }
    __syncthreads();

    // top-9 flag + top-8 softmax (token = tid < 128)
    if (tid < TPB) {
        float* row = logits + tid * LG_STRIDE;
        float vals[TOPK + 1];
        int   inds[TOPK + 1];
#pragma unroll
        for (int s = 0; s < TOPK + 1; s++) {
            float best = -INFINITY;
            int bi = 0;
            for (int j = 0; j < NEXP; j++) {
                float v = row[j];
                if (v > best) { best = v; bi = j; }
            }
            vals[s] = best; inds[s] = bi; row[bi] = -INFINITY;
        }
        bool flag = false;
#pragma unroll
        for (int s = 0; s < TOPK; s++)
            if (vals[s] - vals[s + 1] < TAU) flag = true;
        if (flag) {
            int pos = atomicAdd(&d_flag_count, 1);
            d_flag_list[pos] = tok0 + tid;
        }
        float m = vals[0], e[TOPK], sum = 0.0f;
#pragma unroll
        for (int s = 0; s < TOPK; s++) { e[s] = expf(vals[s] - m); sum += e[s]; }
        float inv = 1.0f / sum;
        for (int j = 0; j < NEXP; j++) row[j] = 0.0f;
#pragma unroll
        for (int s = 0; s < TOPK; s++) {
            row[inds[s]] = e[s] * inv;
            sidx[tid * TOPK + s] = (float)inds[s];
        }
    }
    __syncthreads();

    for (int i = tid; i < TPB * NEXP; i += NTHREADS) {
        int tk = i >> 6, e = i & 63;
        probs_out[(size_t)(tok0 + tk) * NEXP + e] = logits[tk * LG_STRIDE + e];
    }
    if (idx_out)
        for (int i = tid; i < TPB * TOPK; i += NTHREADS)
            idx_out[(size_t)tok0 * TOPK + i] = sidx[i];
}

// ---- fixup: exact Eigen-order recompute, 8 flagged tokens per block pass ----
#define FXT 8
#define FXNT 512
#define FX_XP 0                       // 8*320 = 2560
#define FX_WP 2560                    // 320*65 = 20800
#define FX_LR 23360                   // 512
#define FX_TOK 23872                  // 8
#define SMEM2_FLOATS 23880            // 95520 B

__global__ __launch_bounds__(FXNT)
void router_fixup_kernel(const float* __restrict__ X,
                         const float* __restrict__ W,
                         const float* __restrict__ B,
                         float* __restrict__ probs_out,
                         float* __restrict__ idx_out) {
    extern __shared__ float smem[];
    float* xp = smem + FX_XP;
    float* wp = smem + FX_WP;
    float* lr = smem + FX_LR;
    int* toks = reinterpret_cast<int*>(smem + FX_TOK);
    const int tid = threadIdx.x;
    const int ti = tid >> 6;          // token slot 0..7
    const int e  = tid & 63;          // expert
    const int n = d_flag_count;

    for (int base = blockIdx.x * FXT; base < n; base += gridDim.x * FXT) {
        const int cnt = (n - base < FXT) ? (n - base) : FXT;
        if (tid < cnt) toks[tid] = d_flag_list[base + tid];
        float mst = 0.0f;

#pragma unroll 1
        for (int p = 0; p < 7; p++) {
            const int k0 = p * 320;
            const int len = (p < 6) ? 320 : 128;
            __syncthreads();          // prior compute/select done; toks visible
            if (p < 6) {              // div by constant 320 -> mul/shift
                for (int i = tid; i < NEXP * 320; i += FXNT) {
                    int ee = i / 320, k = i - ee * 320;
                    wp[k * 65 + ee] = W[(size_t)ee * EMBED + k0 + k];
                }
                for (int i = tid; i < cnt * 320; i += FXNT) {
                    int tt = i / 320, k = i - tt * 320;
                    xp[tt * 320 + k] = X[(size_t)toks[tt] * EMBED + k0 + k];
                }
            } else {
                for (int i = tid; i < NEXP * 128; i += FXNT) {
                    int ee = i >> 7, k = i & 127;
                    wp[k * 65 + ee] = W[(size_t)ee * EMBED + k0 + k];
                }
                for (int i = tid; i < cnt * 128; i += FXNT) {
                    int tt = i >> 7, k = i & 127;
                    xp[tt * 320 + k] = X[(size_t)toks[tt] * EMBED + k0 + k];
                }
            }
            __syncthreads();
            if (ti < cnt) {
                float til = 0.0f;
                for (int k = 0; k < len; k++)
                    til = fmaf(xp[ti * 320 + k], wp[k * 65 + e], til);
                mst = mst + til;      // panel flush, ascending panels
            }
        }
        if (ti < cnt) lr[ti * 64 + e] = mst + B[e];
        __syncthreads();

        if (tid < cnt) {
            const int tok = toks[tid];
            float* lrow = lr + tid * 64;
            float vals[TOPK]; int inds[TOPK];
#pragma unroll
            for (int s = 0; s < TOPK; s++) {
                float best = -INFINITY; int bi = 0;
                for (int j = 0; j < NEXP; j++) {
                    float v = lrow[j];
                    if (v > best) { best = v; bi = j; }
                }
                vals[s] = best; inds[s] = bi; lrow[bi] = -INFINITY;
            }
            float m = vals[0], ex[TOPK], sum = 0.0f;
#pragma unroll
            for (int s = 0; s < TOPK; s++) { ex[s] = expf(vals[s] - m); sum += ex[s]; }
            float inv = 1.0f / sum;
            for (int j = 0; j < NEXP; j++) probs_out[(size_t)tok * NEXP + j] = 0.0f;
#pragma unroll
            for (int s = 0; s < TOPK; s++) {
                probs_out[(size_t)tok * NEXP + inds[s]] = ex[s] * inv;
                if (idx_out) idx_out[(size_t)tok * TOPK + s] = (float)inds[s];
            }
        }
        __syncthreads();
    }
}

extern "C" void kernel_launch(void* const* d_in, const int* in_sizes, int n_in,
                              void* d_out, int out_size) {
    const float* X = (const float*)d_in[0];
    const float* W = (const float*)d_in[1];
    const float* B = (const float*)d_in[2];
    float* out = (float*)d_out;

    const long long PROBS_ELEMS = (long long)TOKENS * NEXP;
    const long long IDX_ELEMS   = (long long)TOKENS * TOPK;
    float* idx_out = nullptr;
    if ((long long)out_size >= PROBS_ELEMS + IDX_ELEMS) idx_out = out + PROBS_ELEMS;

    static bool attr_done = false;
    if (!attr_done) {
        cudaFuncSetAttribute(router_main_kernel,
                             cudaFuncAttributeMaxDynamicSharedMemorySize, SMEM1_FLOATS * 4);
        cudaFuncSetAttribute(router_fixup_kernel,
                             cudaFuncAttributeMaxDynamicSharedMemorySize, SMEM2_FLOATS * 4);
        attr_done = true;
    }
    reset_flags_kernel<<<1, 1>>>();
    w_convert_kernel<<<(NEXP * EMBED + 255) / 256, 256>>>(W);
    router_main_kernel<<<TOKENS / TPB, NTHREADS, SMEM1_FLOATS * 4>>>(X, W, B, out, idx_out);
    router_fixup_kernel<<<256, FXNT, SMEM2_FLOATS * 4>>>(X, W, B, out, idx_out);
}

// round 16
// speedup vs baseline: 2.6674x; 2.5469x over previous
#include <cuda_runtime.h>
#include <cuda_bf16.h>
#include <math.h>
#include <stdint.h>

// TopkRouter: logits = X @ W^T + b ; top-8 ; masked softmax.
// X: [32768, 2048] f32, W: [64, 2048] f32, b: [64] f32
// out: probs [32768, 64] f32 then indices [32768, 8] (as f32).
//
// Numerics (FROZEN, matches reference): per output, serial ascending-k fp32
// FMA within 320-wide K panels; master += panel at each boundary
// (k=320,...,1920); 128-wide remainder; bias added at the end.
//
// R16 = R9 (best: 218us) with ONE change: master accumulator lives in smem
// (the logits buffer), freeing 32 registers so ptxas can software-pipeline
// the inner-loop LDS under the FFMA2 stream. Panel flushes are rare (7).

#define TOKENS 32768
#define EMBED 2048
#define NEXP 64
#define TOPK 8
#define TPB 128          // tokens per block
#define KT 32            // k tile
#define NTILES (EMBED / KT)
#define KC_TILES 10      // flush every 10 tiles => panel = 320 (Eigen cap)
#define XS_STRIDE 36     // 16B-aligned rows for LDS.128 over k
#define WS_STRIDE 68     // 64 + 4 pad, 16B-aligned rows
#define LG_STRIDE 65     // logits/master row stride

// dynamic smem layout (floats)
#define XBUF0 0
#define WBUF0 4608                    // 128*36
#define XBUF1 6784                    // +32*68
#define WBUF1 11392
#define MST_OFF 13568                 // 128*65 = 8320 (master acc -> logits)
#define SIDX_OFF 21888                // 128*8
#define SBIAS_OFF 22912               // 64
#define SMEM_FLOATS 22976             // 91904 bytes -> 2 CTA/SM

static __device__ __forceinline__ unsigned long long pack2(float x) {
    unsigned long long r;
    asm("mov.b64 %0, {%1, %1};" : "=l"(r) : "f"(x));
    return r;
}
static __device__ __forceinline__ unsigned long long ffma2(unsigned long long a,
                                                           unsigned long long b,
                                                           unsigned long long c) {
    unsigned long long d;
    asm("fma.rn.f32x2 %0, %1, %2, %3;" : "=l"(d) : "l"(a), "l"(b), "l"(c));
    return d;
}
static __device__ __forceinline__ void unpack2(unsigned long long v, float& lo, float& hi) {
    asm("mov.b64 {%0, %1}, %2;" : "=f"(lo), "=f"(hi) : "l"(v));
}
static __device__ __forceinline__ void cp_async16(uint32_t saddr, const void* g) {
    asm volatile("cp.async.cg.shared.global [%0], [%1], 16;" :: "r"(saddr), "l"(g));
}
static __device__ __forceinline__ void cp_commit() {
    asm volatile("cp.async.commit_group;" ::: "memory");
}
static __device__ __forceinline__ void cp_wait0() {
    asm volatile("cp.async.wait_group 0;" ::: "memory");
}

__global__ __launch_bounds__(256, 2)
void topk_router_kernel(const float* __restrict__ X,
                        const float* __restrict__ W,
                        const float* __restrict__ B,
                        float* __restrict__ probs_out,
                        float* __restrict__ idx_out) {
    extern __shared__ float smem[];
    float* mst   = smem + MST_OFF;    // master accumulator == logits buffer
    float* sidx  = smem + SIDX_OFF;
    float* sbias = smem + SBIAS_OFF;

    const int tid  = threadIdx.x;
    const int tok0 = blockIdx.x * TPB;

    if (tid < NEXP) sbias[tid] = B[tid];
    // zero master accumulator (visible to all by the t=0 __syncthreads)
    for (int i = tid; i < TPB * LG_STRIDE; i += 256) mst[i] = 0.0f;

    const int g = tid >> 3;   // token group: tokens 4g..4g+3
    const int h = tid & 7;    // experts 4h..4h+3 and 32+4h..32+4h+3

    // loader lanes
    const int xt = tid >> 3;          // token row base (0..31), rows xt+32r
    const int xc = tid & 7;           // 4-float chunk
    const float* Xg = X + (size_t)(tok0 + xt) * EMBED + 4 * xc;
    const float* Wg = W + (size_t)xt * EMBED + 4 * xc;   // expert rows xt, xt+32

    // smem byte addresses for the X cp.async destinations, both buffers
    const uint32_t smem_base_b = (uint32_t)__cvta_generic_to_shared(smem);
    uint32_t xdst[2][4];
#pragma unroll
    for (int b = 0; b < 2; b++)
#pragma unroll
        for (int r = 0; r < 4; r++)
            xdst[b][r] = smem_base_b +
                4u * ((b ? XBUF1 : XBUF0) + (uint32_t)(xt + 32 * r) * XS_STRIDE + 4 * xc);

    // panel accumulators only (registers); master is in smem
    unsigned long long til[4][4];
#pragma unroll
    for (int i = 0; i < 4; i++)
#pragma unroll
        for (int j = 0; j < 4; j++) til[i][j] = 0ull;

    float4 wr_[2];

    // prologue: async-load X tile 0, LDG W tile 0
#pragma unroll
    for (int r = 0; r < 4; r++)
        cp_async16(xdst[0][r], Xg + (size_t)(32 * r) * EMBED);
    cp_commit();
#pragma unroll
    for (int r = 0; r < 2; r++)
        wr_[r] = *reinterpret_cast<const float4*>(Wg + (size_t)(32 * r) * EMBED);

    for (int t = 0; t < NTILES; t++) {
        const int buf = t & 1;
        float* Xs = smem + (buf ? XBUF1 : XBUF0);
        float* Ws = smem + (buf ? WBUF1 : WBUF0);

        // store W tile t (transposed)
#pragma unroll
        for (int r = 0; r < 2; r++) {
            int e = xt + 32 * r;
            Ws[(4 * xc + 0) * WS_STRIDE + e] = wr_[r].x;
            Ws[(4 * xc + 1) * WS_STRIDE + e] = wr_[r].y;
            Ws[(4 * xc + 2) * WS_STRIDE + e] = wr_[r].z;
            Ws[(4 * xc + 3) * WS_STRIDE + e] = wr_[r].w;
        }

        cp_wait0();
        __syncthreads();      // tile t visible; tile t-1 compute done

        // issue next tile's loads (hidden under compute of tile t)
        if (t + 1 < NTILES) {
            const float* Xn = Xg + (size_t)(t + 1) * KT;
            const float* Wn = Wg + (size_t)(t + 1) * KT;
#pragma unroll
            for (int r = 0; r < 4; r++)
                cp_async16(xdst[(t + 1) & 1][r], Xn + (size_t)(32 * r) * EMBED);
            cp_commit();
#pragma unroll
            for (int r = 0; r < 2; r++)
                wr_[r] = *reinterpret_cast<const float4*>(Wn + (size_t)(32 * r) * EMBED);
        }

        // ---- compute: serial ascending k within the panel (order frozen) ----
#pragma unroll
        for (int kk4 = 0; kk4 < KT; kk4 += 4) {
            float4 xv0 = *reinterpret_cast<const float4*>(Xs + (4 * g + 0) * XS_STRIDE + kk4);
            float4 xv1 = *reinterpret_cast<const float4*>(Xs + (4 * g + 1) * XS_STRIDE + kk4);
            float4 xv2 = *reinterpret_cast<const float4*>(Xs + (4 * g + 2) * XS_STRIDE + kk4);
            float4 xv3 = *reinterpret_cast<const float4*>(Xs + (4 * g + 3) * XS_STRIDE + kk4);
#pragma unroll
            for (int u = 0; u < 4; u++) {
                const float* wrow = Ws + (kk4 + u) * WS_STRIDE;
                ulonglong2 wa = *reinterpret_cast<const ulonglong2*>(wrow + 4 * h);
                ulonglong2 wb = *reinterpret_cast<const ulonglong2*>(wrow + 32 + 4 * h);
                float x0 = (u == 0) ? xv0.x : (u == 1) ? xv0.y : (u == 2) ? xv0.z : xv0.w;
                float x1 = (u == 0) ? xv1.x : (u == 1) ? xv1.y : (u == 2) ? xv1.z : xv1.w;
                float x2 = (u == 0) ? xv2.x : (u == 1) ? xv2.y : (u == 2) ? xv2.z : xv2.w;
                float x3 = (u == 0) ? xv3.x : (u == 1) ? xv3.y : (u == 2) ? xv3.z : xv3.w;
                unsigned long long xx0 = pack2(x0);
                unsigned long long xx1 = pack2(x1);
                unsigned long long xx2 = pack2(x2);
                unsigned long long xx3 = pack2(x3);
                til[0][0] = ffma2(xx0, wa.x, til[0][0]);
                til[0][1] = ffma2(xx0, wa.y, til[0][1]);
                til[0][2] = ffma2(xx0, wb.x, til[0][2]);
                til[0][3] = ffma2(xx0, wb.y, til[0][3]);
                til[1][0] = ffma2(xx1, wa.x, til[1][0]);
                til[1][1] = ffma2(xx1, wa.y, til[1][1]);
                til[1][2] = ffma2(xx1, wb.x, til[1][2]);
                til[1][3] = ffma2(xx1, wb.y, til[1][3]);
                til[2][0] = ffma2(xx2, wa.x, til[2][0]);
                til[2][1] = ffma2(xx2, wa.y, til[2][1]);
                til[2][2] = ffma2(xx2, wb.x, til[2][2]);
                til[2][3] = ffma2(xx2, wb.y, til[2][3]);
                til[3][0] = ffma2(xx3, wa.x, til[3][0]);
                til[3][1] = ffma2(xx3, wa.y, til[3][1]);
                til[3][2] = ffma2(xx3, wb.x, til[3][2]);
                til[3][3] = ffma2(xx3, wb.y, til[3][3]);
            }
        }

        // ---- Eigen panel boundary (k=320,...,1920): smem master += panel ----
        if ((t + 1) % KC_TILES == 0) {
#pragma unroll
            for (int i = 0; i < 4; i++) {
                float* row = mst + (4 * g + i) * LG_STRIDE;
#pragma unroll
                for (int j = 0; j < 4; j++) {
                    float lo, hi;
                    unpack2(til[i][j], lo, hi);
                    int e = (j < 2) ? (4 * h + 2 * j) : (32 + 4 * h + 2 * (j - 2));
                    row[e]     = row[e]     + lo;
                    row[e + 1] = row[e + 1] + hi;
                    til[i][j] = 0ull;
                }
            }
        }
    }

    // final remainder panel (k = 1920..2047) + bias
    __syncthreads();   // stage buffers dead; also orders last panel flush
#pragma unroll
    for (int i = 0; i < 4; i++) {
        float* row = mst + (4 * g + i) * LG_STRIDE;
#pragma unroll
        for (int j = 0; j < 4; j++) {
            float lo, hi;
            unpack2(til[i][j], lo, hi);
            int e = (j < 2) ? (4 * h + 2 * j) : (32 + 4 * h + 2 * (j - 2));
            row[e]     = (row[e]     + lo) + sbias[e];
            row[e + 1] = (row[e + 1] + hi) + sbias[e + 1];
        }
    }
    __syncthreads();

    // ---- top-8 + masked softmax, one thread per token ----
    if (tid < TPB) {
        float* row = mst + tid * LG_STRIDE;
        float vals[TOPK];
        int   inds[TOPK];
#pragma unroll
        for (int s = 0; s < TOPK; s++) {
            float best = -INFINITY;
            int bi = 0;
            for (int j = 0; j < NEXP; j++) {
                float v = row[j];
                if (v > best) { best = v; bi = j; }   // strict > : lowest index wins ties
            }
            vals[s] = best;
            inds[s] = bi;
            row[bi] = -INFINITY;
        }
        float m = vals[0];
        float e[TOPK];
        float sum = 0.0f;
#pragma unroll
        for (int s = 0; s < TOPK; s++) { e[s] = expf(vals[s] - m); sum += e[s]; }
        float inv = 1.0f / sum;
        for (int j = 0; j < NEXP; j++) row[j] = 0.0f;
#pragma unroll
        for (int s = 0; s < TOPK; s++) {
            row[inds[s]] = e[s] * inv;
            sidx[tid * TOPK + s] = (float)inds[s];
        }
    }
    __syncthreads();

    // ---- coalesced writes ----
    for (int i = tid; i < TPB * NEXP; i += 256) {
        int t = i >> 6;
        int e = i & 63;
        probs_out[(size_t)(tok0 + t) * NEXP + e] = mst[t * LG_STRIDE + e];
    }
    if (idx_out) {
        for (int i = tid; i < TPB * TOPK; i += 256) {
            idx_out[(size_t)tok0 * TOPK + i] = sidx[i];
        }
    }
}

extern "C" void kernel_launch(void* const* d_in, const int* in_sizes, int n_in,
                              void* d_out, int out_size) {
    const float* X = (const float*)d_in[0];
    const float* W = (const float*)d_in[1];
    const float* B = (const float*)d_in[2];
    float* out = (float*)d_out;

    const long long PROBS_ELEMS = (long long)TOKENS * NEXP;   // 2097152
    const long long IDX_ELEMS   = (long long)TOKENS * TOPK;   // 262144
    float* idx_out = nullptr;
    if ((long long)out_size >= PROBS_ELEMS + IDX_ELEMS) idx_out = out + PROBS_ELEMS;

    const int smem_bytes = SMEM_FLOATS * 4;
    cudaFuncSetAttribute(topk_router_kernel,
                         cudaFuncAttributeMaxDynamicSharedMemorySize, smem_bytes);
    topk_router_kernel<<<TOKENS / TPB, 256, smem_bytes>>>(X, W, B, out, idx_out);
}

// round 17
// speedup vs baseline: 2.6694x; 1.0007x over previous
#include <cuda_runtime.h>
#include <cuda_bf16.h>
#include <math.h>
#include <stdint.h>

// TopkRouter: logits = X @ W^T + b ; top-8 ; masked softmax.
// X: [32768, 2048] f32, W: [64, 2048] f32, b: [64] f32
// out: probs [32768, 64] f32 then indices [32768, 8] (as f32).
//
// Numerics (FROZEN, matches reference): per output, serial ascending-k fp32
// FMA within 320-wide K panels; master += panel at each boundary
// (k=320,...,1920); 128-wide remainder; bias added at the end.
//
// R17 = R16 with ONE change: X smem rows skewed by one float4 per token-quad
// (row(t) = t*36 + (t>>2)*4) so the compute-side X LDS.128 hits 4 distinct
// bank-quads {0,20,8,28} -> conflict-free (was structurally 2-way at any
// 16B-aligned flat stride).

#define TOKENS 32768
#define EMBED 2048
#define NEXP 64
#define TOPK 8
#define TPB 128          // tokens per block
#define KT 32            // k tile
#define NTILES (EMBED / KT)
#define KC_TILES 10      // flush every 10 tiles => panel = 320 (Eigen cap)
#define XS_STRIDE 36     // base row stride (plus t>>2 quad skew)
#define WS_STRIDE 68     // 64 + 4 pad, 16B-aligned rows
#define LG_STRIDE 65     // logits/master row stride

// X row offset with quad skew (floats)
#define XROW(t) ((t) * XS_STRIDE + ((t) >> 2) * 4)

// dynamic smem layout (floats)
#define XBUF0 0                       // 128 rows: 127*36+31*4+36 = 4732 -> 4736
#define XBUF1 4736
#define WBUF0 9472                    // 32*68 = 2176
#define WBUF1 11648
#define MST_OFF 13824                 // 128*65 = 8320 (master acc == logits)
#define SIDX_OFF 22144                // 128*8
#define SBIAS_OFF 23168               // 64
#define SMEM_FLOATS 23232             // 92928 bytes -> 2 CTA/SM

static __device__ __forceinline__ unsigned long long pack2(float x) {
    unsigned long long r;
    asm("mov.b64 %0, {%1, %1};" : "=l"(r) : "f"(x));
    return r;
}
static __device__ __forceinline__ unsigned long long ffma2(unsigned long long a,
                                                           unsigned long long b,
                                                           unsigned long long c) {
    unsigned long long d;
    asm("fma.rn.f32x2 %0, %1, %2, %3;" : "=l"(d) : "l"(a), "l"(b), "l"(c));
    return d;
}
static __device__ __forceinline__ void unpack2(unsigned long long v, float& lo, float& hi) {
    asm("mov.b64 {%0, %1}, %2;" : "=f"(lo), "=f"(hi) : "l"(v));
}
static __device__ __forceinline__ void cp_async16(uint32_t saddr, const void* g) {
    asm volatile("cp.async.cg.shared.global [%0], [%1], 16;" :: "r"(saddr), "l"(g));
}
static __device__ __forceinline__ void cp_commit() {
    asm volatile("cp.async.commit_group;" ::: "memory");
}
static __device__ __forceinline__ void cp_wait0() {
    asm volatile("cp.async.wait_group 0;" ::: "memory");
}

__global__ __launch_bounds__(256, 2)
void topk_router_kernel(const float* __restrict__ X,
                        const float* __restrict__ W,
                        const float* __restrict__ B,
                        float* __restrict__ probs_out,
                        float* __restrict__ idx_out) {
    extern __shared__ float smem[];
    float* mst   = smem + MST_OFF;    // master accumulator == logits buffer
    float* sidx  = smem + SIDX_OFF;
    float* sbias = smem + SBIAS_OFF;

    const int tid  = threadIdx.x;
    const int tok0 = blockIdx.x * TPB;

    if (tid < NEXP) sbias[tid] = B[tid];
    // zero master accumulator (visible to all by the t=0 __syncthreads)
    for (int i = tid; i < TPB * LG_STRIDE; i += 256) mst[i] = 0.0f;

    const int g = tid >> 3;   // token group: tokens 4g..4g+3
    const int h = tid & 7;    // experts 4h..4h+3 and 32+4h..32+4h+3

    // loader lanes
    const int xt = tid >> 3;          // token row base (0..31), rows xt+32r
    const int xc = tid & 7;           // 4-float chunk
    const float* Xg = X + (size_t)(tok0 + xt) * EMBED + 4 * xc;
    const float* Wg = W + (size_t)xt * EMBED + 4 * xc;   // expert rows xt, xt+32

    // smem byte addresses for the X cp.async destinations, both buffers (skewed)
    const uint32_t smem_base_b = (uint32_t)__cvta_generic_to_shared(smem);
    uint32_t xdst[2][4];
#pragma unroll
    for (int b = 0; b < 2; b++)
#pragma unroll
        for (int r = 0; r < 4; r++) {
            int t = xt + 32 * r;
            xdst[b][r] = smem_base_b +
                4u * ((b ? XBUF1 : XBUF0) + (uint32_t)XROW(t) + 4 * xc);
        }

    // panel accumulators (registers); master is in smem
    unsigned long long til[4][4];
#pragma unroll
    for (int i = 0; i < 4; i++)
#pragma unroll
        for (int j = 0; j < 4; j++) til[i][j] = 0ull;

    float4 wr_[2];

    // prologue: async-load X tile 0, LDG W tile 0
#pragma unroll
    for (int r = 0; r < 4; r++)
        cp_async16(xdst[0][r], Xg + (size_t)(32 * r) * EMBED);
    cp_commit();
#pragma unroll
    for (int r = 0; r < 2; r++)
        wr_[r] = *reinterpret_cast<const float4*>(Wg + (size_t)(32 * r) * EMBED);

    for (int t = 0; t < NTILES; t++) {
        const int buf = t & 1;
        float* Xs = smem + (buf ? XBUF1 : XBUF0);
        float* Ws = smem + (buf ? WBUF1 : WBUF0);

        // store W tile t (transposed)
#pragma unroll
        for (int r = 0; r < 2; r++) {
            int e = xt + 32 * r;
            Ws[(4 * xc + 0) * WS_STRIDE + e] = wr_[r].x;
            Ws[(4 * xc + 1) * WS_STRIDE + e] = wr_[r].y;
            Ws[(4 * xc + 2) * WS_STRIDE + e] = wr_[r].z;
            Ws[(4 * xc + 3) * WS_STRIDE + e] = wr_[r].w;
        }

        cp_wait0();
        __syncthreads();      // tile t visible; tile t-1 compute done

        // issue next tile's loads (hidden under compute of tile t)
        if (t + 1 < NTILES) {
            const float* Xn = Xg + (size_t)(t + 1) * KT;
            const float* Wn = Wg + (size_t)(t + 1) * KT;
#pragma unroll
            for (int r = 0; r < 4; r++)
                cp_async16(xdst[(t + 1) & 1][r], Xn + (size_t)(32 * r) * EMBED);
            cp_commit();
#pragma unroll
            for (int r = 0; r < 2; r++)
                wr_[r] = *reinterpret_cast<const float4*>(Wn + (size_t)(32 * r) * EMBED);
        }

        // ---- compute: serial ascending k within the panel (order frozen) ----
        // X row base for this thread's 4 tokens: XROW(4g+i) = g*148 + i*36
        const float* Xb = Xs + g * 148;
#pragma unroll
        for (int kk4 = 0; kk4 < KT; kk4 += 4) {
            float4 xv0 = *reinterpret_cast<const float4*>(Xb + 0 * XS_STRIDE + kk4);
            float4 xv1 = *reinterpret_cast<const float4*>(Xb + 1 * XS_STRIDE + kk4);
            float4 xv2 = *reinterpret_cast<const float4*>(Xb + 2 * XS_STRIDE + kk4);
            float4 xv3 = *reinterpret_cast<const float4*>(Xb + 3 * XS_STRIDE + kk4);
#pragma unroll
            for (int u = 0; u < 4; u++) {
                const float* wrow = Ws + (kk4 + u) * WS_STRIDE;
                ulonglong2 wa = *reinterpret_cast<const ulonglong2*>(wrow + 4 * h);
                ulonglong2 wb = *reinterpret_cast<const ulonglong2*>(wrow + 32 + 4 * h);
                float x0 = (u == 0) ? xv0.x : (u == 1) ? xv0.y : (u == 2) ? xv0.z : xv0.w;
                float x1 = (u == 0) ? xv1.x : (u == 1) ? xv1.y : (u == 2) ? xv1.z : xv1.w;
                float x2 = (u == 0) ? xv2.x : (u == 1) ? xv2.y : (u == 2) ? xv2.z : xv2.w;
                float x3 = (u == 0) ? xv3.x : (u == 1) ? xv3.y : (u == 2) ? xv3.z : xv3.w;
                unsigned long long xx0 = pack2(x0);
                unsigned long long xx1 = pack2(x1);
                unsigned long long xx2 = pack2(x2);
                unsigned long long xx3 = pack2(x3);
                til[0][0] = ffma2(xx0, wa.x, til[0][0]);
                til[0][1] = ffma2(xx0, wa.y, til[0][1]);
                til[0][2] = ffma2(xx0, wb.x, til[0][2]);
                til[0][3] = ffma2(xx0, wb.y, til[0][3]);
                til[1][0] = ffma2(xx1, wa.x, til[1][0]);
                til[1][1] = ffma2(xx1, wa.y, til[1][1]);
                til[1][2] = ffma2(xx1, wb.x, til[1][2]);
                til[1][3] = ffma2(xx1, wb.y, til[1][3]);
                til[2][0] = ffma2(xx2, wa.x, til[2][0]);
                til[2][1] = ffma2(xx2, wa.y, til[2][1]);
                til[2][2] = ffma2(xx2, wb.x, til[2][2]);
                til[2][3] = ffma2(xx2, wb.y, til[2][3]);
                til[3][0] = ffma2(xx3, wa.x, til[3][0]);
                til[3][1] = ffma2(xx3, wa.y, til[3][1]);
                til[3][2] = ffma2(xx3, wb.x, til[3][2]);
                til[3][3] = ffma2(xx3, wb.y, til[3][3]);
            }
        }

        // ---- Eigen panel boundary (k=320,...,1920): smem master += panel ----
        if ((t + 1) % KC_TILES == 0) {
#pragma unroll
            for (int i = 0; i < 4; i++) {
                float* row = mst + (4 * g + i) * LG_STRIDE;
#pragma unroll
                for (int j = 0; j < 4; j++) {
                    float lo, hi;
                    unpack2(til[i][j], lo, hi);
                    int e = (j < 2) ? (4 * h + 2 * j) : (32 + 4 * h + 2 * (j - 2));
                    row[e]     = row[e]     + lo;
                    row[e + 1] = row[e + 1] + hi;
                    til[i][j] = 0ull;
                }
            }
        }
    }

    // final remainder panel (k = 1920..2047) + bias
    __syncthreads();   // stage buffers dead; also orders last panel flush
#pragma unroll
    for (int i = 0; i < 4; i++) {
        float* row = mst + (4 * g + i) * LG_STRIDE;
#pragma unroll
        for (int j = 0; j < 4; j++) {
            float lo, hi;
            unpack2(til[i][j], lo, hi);
            int e = (j < 2) ? (4 * h + 2 * j) : (32 + 4 * h + 2 * (j - 2));
            row[e]     = (row[e]     + lo) + sbias[e];
            row[e + 1] = (row[e + 1] + hi) + sbias[e + 1];
        }
    }
    __syncthreads();

    // ---- top-8 + masked softmax, one thread per token ----
    if (tid < TPB) {
        float* row = mst + tid * LG_STRIDE;
        float vals[TOPK];
        int   inds[TOPK];
#pragma unroll
        for (int s = 0; s < TOPK; s++) {
            float best = -INFINITY;
            int bi = 0;
            for (int j = 0; j < NEXP; j++) {
                float v = row[j];
                if (v > best) { best = v; bi = j; }   // strict > : lowest index wins ties
            }
            vals[s] = best;
            inds[s] = bi;
            row[bi] = -INFINITY;
        }
        float m = vals[0];
        float e[TOPK];
        float sum = 0.0f;
#pragma unroll
        for (int s = 0; s < TOPK; s++) { e[s] = expf(vals[s] - m); sum += e[s]; }
        float inv = 1.0f / sum;
        for (int j = 0; j < NEXP; j++) row[j] = 0.0f;
#pragma unroll
        for (int s = 0; s < TOPK; s++) {
            row[inds[s]] = e[s] * inv;
            sidx[tid * TOPK + s] = (float)inds[s];
        }
    }
    __syncthreads();

    // ---- coalesced writes ----
    for (int i = tid; i < TPB * NEXP; i += 256) {
        int t = i >> 6;
        int e = i & 63;
        probs_out[(size_t)(tok0 + t) * NEXP + e] = mst[t * LG_STRIDE + e];
    }
    if (idx_out) {
        for (int i = tid; i < TPB * TOPK; i += 256) {
            idx_out[(size_t)tok0 * TOPK + i] = sidx[i];
        }
    }
}

extern "C" void kernel_launch(void* const* d_in, const int* in_sizes, int n_in,
                              void* d_out, int out_size) {
    const float* X = (const float*)d_in[0];
    const float* W = (const float*)d_in[1];
    const float* B = (const float*)d_in[2];
    float* out = (float*)d_out;

    const long long PROBS_ELEMS = (long long)TOKENS * NEXP;   // 2097152
    const long long IDX_ELEMS   = (long long)TOKENS * TOPK;   // 262144
    float* idx_out = nullptr;
    if ((long long)out_size >= PROBS_ELEMS + IDX_ELEMS) idx_out = out + PROBS_ELEMS;

    const int smem_bytes = SMEM_FLOATS * 4;
    cudaFuncSetAttribute(topk_router_kernel,
                         cudaFuncAttributeMaxDynamicSharedMemorySize, smem_bytes);
    topk_router_kernel<<<TOKENS / TPB, 256, smem_bytes>>>(X, W, B, out, idx_out);
}